// round 15
// baseline (speedup 1.0000x reference)
#include <cuda_runtime.h>
#include <cuda_bf16.h>
#include <stdint.h>
#include <math.h>

// ---------------------------------------------------------------------------
// Problem constants
#define NROW 8192
#define DDIM 256
#define NCLS 512
// Features scaled by sqrt(log2e / T): MMA emits LOG2-domain logits.
#define SCALE_LG 4.53981534f
#define LOG2E_INVT 20.60992337f
#define LN2F 0.69314718f

#define BM 128
#define NB (NROW / BM)                 // 64 blocks
#define NPAIRS (NB * (NB + 1) / 2)     // 2080 tile pairs
#define NOFF (NPAIRS - NB)             // 2016 strict off-diagonal pairs
#define NTHREADS 256

// SMEM: 4 x 16KB chunk buffers (A double-buffered, B double-buffered).
#define CHUNK 16384
#define SM_TOTAL 65536

// Finalize: 8 warps/block, 4 rows/warp -> 32 rows/block -> 256 blocks.
#define FIN_BLOCKS (NROW / 32)

// Device-global scratch (no cudaMalloc allowed)
__device__ __nv_bfloat16 g_fb[NROW * DDIM];   // scaled bf16 features, 4 MB
__device__ float g_sv[NCLS * DDIM];           // class sum vectors (fp32)
__device__ int   g_cnt[NCLS];                 // class histogram (zeroed on exit)
__device__ int   g_lab[NROW];
__device__ float g_S[NROW];                   // sum exp (zeroed on exit)
__device__ float g_sum;                       // (zeroed on exit)
__device__ int   g_done;                      // finalize done counter

// ---------------------------------------------------------------------------
// PTX helpers (sm_80/90-era only: safe for plain sm_103 ptx target)
// ---------------------------------------------------------------------------
__device__ __forceinline__ uint32_t smem_u32(const void* p) {
    uint32_t a;
    asm("{ .reg .u64 t; cvta.to.shared.u64 t, %1; cvt.u32.u64 %0, t; }"
        : "=r"(a) : "l"(p));
    return a;
}

__device__ __forceinline__ void ldsm_x4(uint32_t* r, uint32_t addr) {
    asm volatile("ldmatrix.sync.aligned.m8n8.x4.shared.b16 {%0,%1,%2,%3}, [%4];"
        : "=r"(r[0]), "=r"(r[1]), "=r"(r[2]), "=r"(r[3]) : "r"(addr));
}

__device__ __forceinline__ void mma_bf16(float* c, const uint32_t* a,
                                         uint32_t b0, uint32_t b1) {
    asm volatile("mma.sync.aligned.m16n8k16.row.col.f32.bf16.bf16.f32 "
        "{%0,%1,%2,%3},{%4,%5,%6,%7},{%8,%9},{%0,%1,%2,%3};"
        : "+f"(c[0]), "+f"(c[1]), "+f"(c[2]), "+f"(c[3])
        : "r"(a[0]), "r"(a[1]), "r"(a[2]), "r"(a[3]), "r"(b0), "r"(b1));
}

__device__ __forceinline__ void cp16(uint32_t dst, const void* src) {
    asm volatile("cp.async.cg.shared.global [%0], [%1], 16;"
                 :: "r"(dst), "l"(src) : "memory");
}
#define CP_COMMIT() asm volatile("cp.async.commit_group;" ::: "memory")
#define CP_WAIT0()  asm volatile("cp.async.wait_group 0;" ::: "memory")
#define CP_WAIT1()  asm volatile("cp.async.wait_group 1;" ::: "memory")

__device__ __forceinline__ float ex2f(float x) {
    float r;
    asm("ex2.approx.f32 %0, %1;" : "=f"(r) : "f"(x));
    return r;
}

// Vector reductions (sm_90+ PTX).
__device__ __forceinline__ void red_add_v4(float* addr, float a, float b,
                                           float c, float d) {
    asm volatile("red.global.add.v4.f32 [%0], {%1, %2, %3, %4};"
                 :: "l"(addr), "f"(a), "f"(b), "f"(c), "f"(d) : "memory");
}
__device__ __forceinline__ void red_add_v2(float* addr, float a, float b) {
    asm volatile("red.global.add.v2.f32 [%0], {%1, %2};"
                 :: "l"(addr), "f"(a), "f"(b) : "memory");
}

// Programmatic dependent launch (sm_90+).
#define PDL_TRIGGER() asm volatile("griddepcontrol.launch_dependents;" ::: "memory")
#define PDL_WAIT()    asm volatile("griddepcontrol.wait;" ::: "memory")

// ---------------------------------------------------------------------------
// Kernel 0: zero g_sv + label dtype detect + labels + histogram.
// Triggers dependents immediately: prep's pre-wait phase touches no init data.
// ---------------------------------------------------------------------------
__global__ void init_kernel(const unsigned* __restrict__ lab32) {
    PDL_TRIGGER();

    __shared__ int any;
    if (threadIdx.x == 0) any = 0;
    __syncthreads();
    int local = 0;
    for (int i = threadIdx.x; i < 4096; i += 256)
        local |= (lab32[2 * i + 1] != 0u);
    if (local) atomicOr(&any, 1);
    __syncthreads();

    int row = blockIdx.x * 256 + threadIdx.x;
    int lv;
    if (any) lv = ((const int*)lab32)[row];
    else     lv = (int)((const long long*)lab32)[row];
    g_lab[row] = lv;
    atomicAdd(&g_cnt[lv], 1);

    const int n = 32 * 256;
    for (int i = row; i < NCLS * DDIM; i += n) g_sv[i] = 0.0f;
}

// ---------------------------------------------------------------------------
// Kernel 1: L2-normalize rows -> bf16; class-sum v4 red. One warp per row.
// Pre-wait: feature loads + norm + g_fb write (no init dependency).
// Post-wait: g_lab read + g_sv reductions (racy with init's zeroing otherwise).
// ---------------------------------------------------------------------------
__global__ void prep_kernel(const float* __restrict__ f) {
    PDL_TRIGGER();

    int row  = blockIdx.x * 8 + (threadIdx.x >> 5);
    int lane = threadIdx.x & 31;

    const float4* fr = reinterpret_cast<const float4*>(f + (size_t)row * DDIM);
    float4 v0 = fr[lane];
    float4 v1 = fr[lane + 32];

    float ss = v0.x*v0.x + v0.y*v0.y + v0.z*v0.z + v0.w*v0.w
             + v1.x*v1.x + v1.y*v1.y + v1.z*v1.z + v1.w*v1.w;
    #pragma unroll
    for (int o = 16; o > 0; o >>= 1) ss += __shfl_xor_sync(0xFFFFFFFFu, ss, o);

    float s = SCALE_LG / fmaxf(sqrtf(ss), 1e-12f);

    float a0 = v0.x * s, a1 = v0.y * s, a2 = v0.z * s, a3 = v0.w * s;
    float b0 = v1.x * s, b1 = v1.y * s, b2 = v1.z * s, b3 = v1.w * s;

    __nv_bfloat162 p0 = __floats2bfloat162_rn(a0, a1);
    __nv_bfloat162 p1 = __floats2bfloat162_rn(a2, a3);
    __nv_bfloat162 p2 = __floats2bfloat162_rn(b0, b1);
    __nv_bfloat162 p3 = __floats2bfloat162_rn(b2, b3);
    uint2 w0, w1;
    w0.x = *reinterpret_cast<uint32_t*>(&p0);
    w0.y = *reinterpret_cast<uint32_t*>(&p1);
    w1.x = *reinterpret_cast<uint32_t*>(&p2);
    w1.y = *reinterpret_cast<uint32_t*>(&p3);
    *reinterpret_cast<uint2*>(&g_fb[(size_t)row * DDIM + lane * 4])       = w0;
    *reinterpret_cast<uint2*>(&g_fb[(size_t)row * DDIM + 128 + lane * 4]) = w1;

    PDL_WAIT();      // init complete: g_lab valid, g_sv zeroed

    int lab = g_lab[row];
    float* sv = g_sv + lab * DDIM;
    red_add_v4(&sv[lane * 4],       a0, a1, a2, a3);
    red_add_v4(&sv[128 + lane * 4], b0, b1, b2, b3);
}

// ---------------------------------------------------------------------------
// cp.async one 16KB K-chunk: 128 rows x 128B; source row stride 512B.
// ---------------------------------------------------------------------------
__device__ __forceinline__ void load_chunk(uint32_t base, const char* gsrc) {
    const int tid = threadIdx.x;
    #pragma unroll
    for (int q = 0; q < 4; q++) {
        int idx = q * NTHREADS + tid;          // 0..1023
        int row = idx >> 3;
        int c   = idx & 7;
        uint32_t dst = base + row * 128 + ((c ^ (row & 7)) << 4);
        cp16(dst, gsrc + row * 512 + c * 16);
    }
}

// ---------------------------------------------------------------------------
// Kernel 2: symmetric bf16 GEMM + exp-only (ex2) epilogue into g_S.
// Grid NPAIRS, 2 CTAs/SM. Off-diagonal pairs first (idx 0..2015, bi<bj);
// diagonal tiles last (idx 2016..2079) -> cheap tiles close the tail.
// ---------------------------------------------------------------------------
__global__ __launch_bounds__(NTHREADS, 2)
void supcon_s_kernel() {
    extern __shared__ char smem[];
    const uint32_t sbase = smem_u32(smem);

    // Decode blockIdx.x: diag tiles mapped to the last NB indices.
    const int idx = blockIdx.x;
    int bi, bj;
    if (idx >= NOFF) {
        bi = bj = idx - NOFF;
    } else {
        // Strict pairs bi<bj; C(b) = b*NB - b*(b+1)/2.
        const float fn = 2.0f * NB - 1.0f;
        int b = (int)((fn - sqrtf(fn * fn - 8.0f * idx)) * 0.5f);
        if (b < 0) b = 0;
        if (b > NB - 2) b = NB - 2;
        while (b * NB - (b * (b + 1) >> 1) > idx) b--;
        while ((b + 1) * NB - ((b + 1) * (b + 2) >> 1) <= idx) b++;
        bi = b;
        bj = b + 1 + (idx - (b * NB - (b * (b + 1) >> 1)));
    }
    const bool diag = (bi == bj);

    const int row0 = bi * BM;
    const int col0 = bj * BM;

    const int lane   = threadIdx.x & 31;
    const int wid    = threadIdx.x >> 5;
    const int warp_m = wid & 3;
    const int warp_n = wid >> 2;
    const int laneM  = lane & 15;
    const int laneC  = lane >> 4;
    const int rq     = lane >> 2;
    const int cq     = lane & 3;

    int gRow[4];
    #pragma unroll
    for (int mi = 0; mi < 2; mi++)
        #pragma unroll
        for (int s = 0; s < 2; s++)
            gRow[mi * 2 + s] = row0 + warp_m * 32 + mi * 16 + s * 8 + rq;

    PDL_WAIT();      // prep complete: g_fb valid
    PDL_TRIGGER();   // (after wait!) finalize may start its prep-dependent dots

    const char* gfb  = reinterpret_cast<const char*>(g_fb);
    const char* aSrc = gfb + (size_t)row0 * 512;
    const char* bSrc = gfb + (size_t)col0 * 512;

    // Prologue: fill both buffer pairs (chunks 0 and 1).
    load_chunk(sbase + 0 * CHUNK, aSrc);
    if (!diag) load_chunk(sbase + 2 * CHUNK, bSrc);
    CP_COMMIT();
    load_chunk(sbase + 1 * CHUNK, aSrc + 128);
    if (!diag) load_chunk(sbase + 3 * CHUNK, bSrc + 128);
    CP_COMMIT();

    float c[2][8][4];
    #pragma unroll
    for (int mi = 0; mi < 2; mi++)
        #pragma unroll
        for (int nj = 0; nj < 8; nj++)
            #pragma unroll
            for (int e = 0; e < 4; e++) c[mi][nj][e] = 0.f;

    #pragma unroll
    for (int kc = 0; kc < 4; kc++) {
        const int p = kc & 1;

        if (kc > 0) {
            __syncthreads();           // all warps done reading buffers p^1
            if (kc < 3) {
                load_chunk(sbase + (p ^ 1) * CHUNK, aSrc + (kc + 1) * 128);
                if (!diag)
                    load_chunk(sbase + (2 + (p ^ 1)) * CHUNK, bSrc + (kc + 1) * 128);
                CP_COMMIT();
            }
        }
        if (kc < 3) CP_WAIT1(); else CP_WAIT0();
        __syncthreads();

        const uint32_t bufA = sbase + p * CHUNK;
        const uint32_t bufB = diag ? bufA : (sbase + (2 + p) * CHUNK);

        #pragma unroll
        for (int ks = 0; ks < 4; ks++) {
            const int ch = ks * 2 + laneC;
            uint32_t a0[4], a1[4];
            {
                int r = warp_m * 32 + laneM;
                ldsm_x4(a0, bufA + r * 128 + ((ch ^ (r & 7)) << 4));
                int r2 = r + 16;
                ldsm_x4(a1, bufA + r2 * 128 + ((ch ^ (r2 & 7)) << 4));
            }
            #pragma unroll
            for (int ng = 0; ng < 4; ng++) {
                uint32_t bf[4];
                int nr = warp_n * 64 + ng * 16 + laneM;
                ldsm_x4(bf, bufB + nr * 128 + ((ch ^ (nr & 7)) << 4));
                mma_bf16(c[0][ng * 2],     a0, bf[0], bf[2]);
                mma_bf16(c[0][ng * 2 + 1], a0, bf[1], bf[3]);
                mma_bf16(c[1][ng * 2],     a1, bf[0], bf[2]);
                mma_bf16(c[1][ng * 2 + 1], a1, bf[1], bf[3]);
            }
        }
    }

    // ---- Epilogue: S only; accumulators are log2-domain -> raw ex2. ----
    float accS[4] = {0.f, 0.f, 0.f, 0.f};

    if (diag) {
        #pragma unroll
        for (int nj = 0; nj < 8; nj++) {
            const int gj0 = col0 + warp_n * 64 + nj * 8 + cq * 2;
            #pragma unroll
            for (int mi = 0; mi < 2; mi++) {
                #pragma unroll
                for (int s = 0; s < 2; s++) {
                    const int i4 = mi * 2 + s;
                    const int gi = gRow[i4];
                    float e0 = ex2f(c[mi][nj][s * 2 + 0]);
                    float e1 = ex2f(c[mi][nj][s * 2 + 1]);
                    if (gi != gj0)     accS[i4] += e0;
                    if (gi != gj0 + 1) accS[i4] += e1;
                }
            }
        }
    } else {
        float colS[16];
        #pragma unroll
        for (int i = 0; i < 16; i++) colS[i] = 0.f;

        #pragma unroll
        for (int nj = 0; nj < 8; nj++) {
            #pragma unroll
            for (int mi = 0; mi < 2; mi++) {
                #pragma unroll
                for (int s = 0; s < 2; s++) {
                    const int i4 = mi * 2 + s;
                    float e0 = ex2f(c[mi][nj][s * 2 + 0]);
                    float e1 = ex2f(c[mi][nj][s * 2 + 1]);
                    accS[i4] += e0 + e1;
                    colS[nj * 2]     += e0;
                    colS[nj * 2 + 1] += e1;
                }
            }
        }

        #pragma unroll
        for (int i = 0; i < 16; i++) {
            colS[i] += __shfl_xor_sync(0xFFFFFFFFu, colS[i], 4);
            colS[i] += __shfl_xor_sync(0xFFFFFFFFu, colS[i], 8);
            colS[i] += __shfl_xor_sync(0xFFFFFFFFu, colS[i], 16);
        }
        if (lane < 4) {
            #pragma unroll
            for (int nj = 0; nj < 8; nj++) {
                red_add_v2(&g_S[col0 + warp_n * 64 + nj * 8 + lane * 2],
                           colS[nj * 2], colS[nj * 2 + 1]);
            }
        }
    }

    #pragma unroll
    for (int i = 0; i < 4; i++) {
        accS[i] += __shfl_xor_sync(0xFFFFFFFFu, accS[i], 1);
        accS[i] += __shfl_xor_sync(0xFFFFFFFFu, accS[i], 2);
    }
    if (cq == 0) {
        #pragma unroll
        for (int i = 0; i < 4; i++)
            atomicAdd(&g_S[gRow[i]], accS[i]);
    }
}

// ---------------------------------------------------------------------------
// Kernel 3: per-row term via class sums. Dot phase (g_fb . g_sv, both
// prep-dependent and valid once main has started) runs PRE-wait, fully
// overlapped with the main kernel. Post-wait: g_S terms + scalar + cleanup.
// ---------------------------------------------------------------------------
__global__ void finalize_kernel(float* __restrict__ out) {
    const int warp  = threadIdx.x >> 5;
    const int lane  = threadIdx.x & 31;
    const int rbase = blockIdx.x * 32 + warp * 4;

    int   lab[4];
    uint4 bv[4];
    float4 s0[4], s1[4];
    #pragma unroll
    for (int r = 0; r < 4; r++) lab[r] = g_lab[rbase + r];
    #pragma unroll
    for (int r = 0; r < 4; r++) {
        bv[r] = *reinterpret_cast<const uint4*>(
            &g_fb[(size_t)(rbase + r) * DDIM + lane * 8]);
        s0[r] = *reinterpret_cast<const float4*>(&g_sv[lab[r] * DDIM + lane * 8]);
        s1[r] = *reinterpret_cast<const float4*>(&g_sv[lab[r] * DDIM + lane * 8 + 4]);
    }

    float d[4];
    #pragma unroll
    for (int r = 0; r < 4; r++) {
        const __nv_bfloat162* bp = reinterpret_cast<const __nv_bfloat162*>(&bv[r]);
        float2 f0 = __bfloat1622float2(bp[0]);
        float2 f1 = __bfloat1622float2(bp[1]);
        float2 f2 = __bfloat1622float2(bp[2]);
        float2 f3 = __bfloat1622float2(bp[3]);

        float dd = f0.x * s0[r].x + f0.y * s0[r].y + f1.x * s0[r].z + f1.y * s0[r].w
                 + f2.x * s1[r].x + f2.y * s1[r].y + f3.x * s1[r].z + f3.y * s1[r].w;
        #pragma unroll
        for (int o = 16; o > 0; o >>= 1) dd += __shfl_xor_sync(0xFFFFFFFFu, dd, o);
        d[r] = dd;
    }

    PDL_WAIT();      // main complete: g_S valid

    float tsum = 0.0f;
    if (lane == 0) {
        #pragma unroll
        for (int r = 0; r < 4; r++) {
            float P  = (d[r] - LOG2E_INVT) * LN2F;
            float Cf = (float)(g_cnt[lab[r]] - 1);
            float lz = __logf(g_S[rbase + r] + 1e-6f);
            tsum += (P - Cf * lz) / fmaxf(Cf, 1.0f);
            g_S[rbase + r] = 0.0f;      // zero-on-exit for next replay
        }
    }

    __shared__ float ws[8];
    __shared__ int   isLast;
    if (lane == 0) ws[warp] = tsum;
    __syncthreads();
    if (threadIdx.x == 0) {
        float s = 0.f;
        #pragma unroll
        for (int w = 0; w < 8; w++) s += ws[w];
        atomicAdd(&g_sum, s);
        __threadfence();
        int d_ = atomicAdd(&g_done, 1);
        isLast = (d_ == gridDim.x - 1);
    }
    __syncthreads();
    if (isLast) {
        if (threadIdx.x == 0) {
            __threadfence();
            out[0] = -g_sum / (float)NROW;
            g_sum  = 0.0f;
            g_done = 0;
        }
        for (int i = threadIdx.x; i < NCLS; i += 256) g_cnt[i] = 0;
    }
}

// ---------------------------------------------------------------------------
extern "C" void kernel_launch(void* const* d_in, const int* in_sizes, int n_in,
                              void* d_out, int out_size) {
    const float* feats = (const float*)d_in[0];
    const void*  labs  = d_in[1];
    float*       out   = (float*)d_out;

    cudaFuncSetAttribute(supcon_s_kernel,
                         cudaFuncAttributeMaxDynamicSharedMemorySize, SM_TOTAL);

    init_kernel<<<NROW / 256, 256>>>((const unsigned*)labs);

    cudaLaunchAttribute at[1];
    at[0].id = cudaLaunchAttributeProgrammaticStreamSerialization;
    at[0].val.programmaticStreamSerializationAllowed = 1;

    cudaLaunchConfig_t cfg = {};
    cfg.blockDim = {NTHREADS, 1, 1};
    cfg.attrs    = at;
    cfg.numAttrs = 1;

    cfg.gridDim = {NROW / 8, 1, 1};
    cudaLaunchKernelEx(&cfg, prep_kernel, feats);

    cfg.gridDim = {NPAIRS, 1, 1};
    cfg.dynamicSmemBytes = SM_TOTAL;
    cudaLaunchKernelEx(&cfg, supcon_s_kernel);
    cfg.dynamicSmemBytes = 0;

    cfg.gridDim = {FIN_BLOCKS, 1, 1};
    cudaLaunchKernelEx(&cfg, finalize_kernel, out);
}

// round 16
// speedup vs baseline: 1.1495x; 1.1495x over previous
#include <cuda_runtime.h>
#include <cuda_bf16.h>
#include <stdint.h>
#include <math.h>

// ---------------------------------------------------------------------------
// Problem constants
#define NROW 8192
#define DDIM 256
#define NCLS 512
// Features scaled by sqrt(log2e / T): MMA emits LOG2-domain logits.
#define SCALE_LG 4.53981534f
#define LOG2E_INVT 20.60992337f
#define LN2F 0.69314718f

#define BM 128
#define NB (NROW / BM)                 // 64 blocks
#define NPAIRS (NB * (NB + 1) / 2)     // 2080 tile pairs
#define NOFF (NPAIRS - NB)             // 2016 strict off-diagonal pairs
#define NTHREADS 256

// SMEM: 4 x 16KB chunk buffers (A double-buffered, B double-buffered).
#define CHUNK 16384
#define SM_TOTAL 65536

// Finalize: 8 warps/block, 4 rows/warp -> 32 rows/block -> 256 blocks.
#define FIN_BLOCKS (NROW / 32)

// Device-global scratch (no cudaMalloc allowed)
__device__ __nv_bfloat16 g_fb[NROW * DDIM];   // scaled bf16 features, 4 MB
__device__ float g_sv[NCLS * DDIM];           // class sum vectors (fp32)
__device__ int   g_cnt[NCLS];                 // class histogram (zeroed on exit)
__device__ int   g_lab[NROW];
__device__ float g_S[NROW];                   // sum exp (zeroed on exit)
__device__ float g_sum;                       // (zeroed on exit)
__device__ int   g_done;                      // finalize done counter

// ---------------------------------------------------------------------------
// PTX helpers (sm_80/90-era only: safe for plain sm_103 ptx target)
// ---------------------------------------------------------------------------
__device__ __forceinline__ uint32_t smem_u32(const void* p) {
    uint32_t a;
    asm("{ .reg .u64 t; cvta.to.shared.u64 t, %1; cvt.u32.u64 %0, t; }"
        : "=r"(a) : "l"(p));
    return a;
}

__device__ __forceinline__ void ldsm_x4(uint32_t* r, uint32_t addr) {
    asm volatile("ldmatrix.sync.aligned.m8n8.x4.shared.b16 {%0,%1,%2,%3}, [%4];"
        : "=r"(r[0]), "=r"(r[1]), "=r"(r[2]), "=r"(r[3]) : "r"(addr));
}

__device__ __forceinline__ void mma_bf16(float* c, const uint32_t* a,
                                         uint32_t b0, uint32_t b1) {
    asm volatile("mma.sync.aligned.m16n8k16.row.col.f32.bf16.bf16.f32 "
        "{%0,%1,%2,%3},{%4,%5,%6,%7},{%8,%9},{%0,%1,%2,%3};"
        : "+f"(c[0]), "+f"(c[1]), "+f"(c[2]), "+f"(c[3])
        : "r"(a[0]), "r"(a[1]), "r"(a[2]), "r"(a[3]), "r"(b0), "r"(b1));
}

__device__ __forceinline__ void cp16(uint32_t dst, const void* src) {
    asm volatile("cp.async.cg.shared.global [%0], [%1], 16;"
                 :: "r"(dst), "l"(src) : "memory");
}
#define CP_COMMIT() asm volatile("cp.async.commit_group;" ::: "memory")
#define CP_WAIT0()  asm volatile("cp.async.wait_group 0;" ::: "memory")
#define CP_WAIT1()  asm volatile("cp.async.wait_group 1;" ::: "memory")

__device__ __forceinline__ float ex2f(float x) {
    float r;
    asm("ex2.approx.f32 %0, %1;" : "=f"(r) : "f"(x));
    return r;
}

// Vector reductions (sm_90+ PTX).
__device__ __forceinline__ void red_add_v4(float* addr, float a, float b,
                                           float c, float d) {
    asm volatile("red.global.add.v4.f32 [%0], {%1, %2, %3, %4};"
                 :: "l"(addr), "f"(a), "f"(b), "f"(c), "f"(d) : "memory");
}
__device__ __forceinline__ void red_add_v2(float* addr, float a, float b) {
    asm volatile("red.global.add.v2.f32 [%0], {%1, %2};"
                 :: "l"(addr), "f"(a), "f"(b) : "memory");
}

// Programmatic dependent launch (sm_90+). Used ONLY for init -> prep: the
// waiting grid (prep) has heavy pre-wait work and init is tiny, so the
// resident-waiter contention that sank R15's main/finalize overlap is absent.
#define PDL_TRIGGER() asm volatile("griddepcontrol.launch_dependents;" ::: "memory")
#define PDL_WAIT()    asm volatile("griddepcontrol.wait;" ::: "memory")

// ---------------------------------------------------------------------------
// Kernel 0: zero g_sv + label dtype detect + labels + histogram.
// Triggers dependents immediately: prep's pre-wait phase touches no init data.
// ---------------------------------------------------------------------------
__global__ void init_kernel(const unsigned* __restrict__ lab32) {
    PDL_TRIGGER();

    __shared__ int any;
    if (threadIdx.x == 0) any = 0;
    __syncthreads();
    int local = 0;
    for (int i = threadIdx.x; i < 4096; i += 256)
        local |= (lab32[2 * i + 1] != 0u);
    if (local) atomicOr(&any, 1);
    __syncthreads();

    int row = blockIdx.x * 256 + threadIdx.x;
    int lv;
    if (any) lv = ((const int*)lab32)[row];
    else     lv = (int)((const long long*)lab32)[row];
    g_lab[row] = lv;
    atomicAdd(&g_cnt[lv], 1);

    const int n = 32 * 256;
    for (int i = row; i < NCLS * DDIM; i += n) g_sv[i] = 0.0f;
}

// ---------------------------------------------------------------------------
// Kernel 1: L2-normalize rows -> bf16; class-sum v4 red. One warp per row.
// Pre-wait: feature loads + norm + g_fb write. Post-wait: g_lab / g_sv.
// ---------------------------------------------------------------------------
__global__ void prep_kernel(const float* __restrict__ f) {
    int row  = blockIdx.x * 8 + (threadIdx.x >> 5);
    int lane = threadIdx.x & 31;

    const float4* fr = reinterpret_cast<const float4*>(f + (size_t)row * DDIM);
    float4 v0 = fr[lane];
    float4 v1 = fr[lane + 32];

    float ss = v0.x*v0.x + v0.y*v0.y + v0.z*v0.z + v0.w*v0.w
             + v1.x*v1.x + v1.y*v1.y + v1.z*v1.z + v1.w*v1.w;
    #pragma unroll
    for (int o = 16; o > 0; o >>= 1) ss += __shfl_xor_sync(0xFFFFFFFFu, ss, o);

    float s = SCALE_LG / fmaxf(sqrtf(ss), 1e-12f);

    float a0 = v0.x * s, a1 = v0.y * s, a2 = v0.z * s, a3 = v0.w * s;
    float b0 = v1.x * s, b1 = v1.y * s, b2 = v1.z * s, b3 = v1.w * s;

    __nv_bfloat162 p0 = __floats2bfloat162_rn(a0, a1);
    __nv_bfloat162 p1 = __floats2bfloat162_rn(a2, a3);
    __nv_bfloat162 p2 = __floats2bfloat162_rn(b0, b1);
    __nv_bfloat162 p3 = __floats2bfloat162_rn(b2, b3);
    uint2 w0, w1;
    w0.x = *reinterpret_cast<uint32_t*>(&p0);
    w0.y = *reinterpret_cast<uint32_t*>(&p1);
    w1.x = *reinterpret_cast<uint32_t*>(&p2);
    w1.y = *reinterpret_cast<uint32_t*>(&p3);
    *reinterpret_cast<uint2*>(&g_fb[(size_t)row * DDIM + lane * 4])       = w0;
    *reinterpret_cast<uint2*>(&g_fb[(size_t)row * DDIM + 128 + lane * 4]) = w1;

    PDL_WAIT();      // init complete: g_lab valid, g_sv zeroed

    int lab = g_lab[row];
    float* sv = g_sv + lab * DDIM;
    red_add_v4(&sv[lane * 4],       a0, a1, a2, a3);
    red_add_v4(&sv[128 + lane * 4], b0, b1, b2, b3);
}

// ---------------------------------------------------------------------------
// cp.async one 16KB K-chunk: 128 rows x 128B; source row stride 512B.
// ---------------------------------------------------------------------------
__device__ __forceinline__ void load_chunk(uint32_t base, const char* gsrc) {
    const int tid = threadIdx.x;
    #pragma unroll
    for (int q = 0; q < 4; q++) {
        int idx = q * NTHREADS + tid;          // 0..1023
        int row = idx >> 3;
        int c   = idx & 7;
        uint32_t dst = base + row * 128 + ((c ^ (row & 7)) << 4);
        cp16(dst, gsrc + row * 512 + c * 16);
    }
}

// ---------------------------------------------------------------------------
// Kernel 2: symmetric bf16 GEMM + exp-only (ex2) epilogue into g_S.
// Grid NPAIRS, 2 CTAs/SM. Off-diagonal pairs first (idx 0..2015, bi<bj);
// diagonal tiles last -> the cheap, B-load-free tiles close the tail wave.
// ---------------------------------------------------------------------------
__global__ __launch_bounds__(NTHREADS, 2)
void supcon_s_kernel() {
    extern __shared__ char smem[];
    const uint32_t sbase = smem_u32(smem);

    // Decode blockIdx.x: diag tiles mapped to the last NB indices.
    const int idx = blockIdx.x;
    int bi, bj;
    if (idx >= NOFF) {
        bi = bj = idx - NOFF;
    } else {
        // Strict pairs bi<bj; C(b) = b*NB - b*(b+1)/2.
        const float fn = 2.0f * NB - 1.0f;
        int b = (int)((fn - sqrtf(fn * fn - 8.0f * idx)) * 0.5f);
        if (b < 0) b = 0;
        if (b > NB - 2) b = NB - 2;
        while (b * NB - (b * (b + 1) >> 1) > idx) b--;
        while ((b + 1) * NB - ((b + 1) * (b + 2) >> 1) <= idx) b++;
        bi = b;
        bj = b + 1 + (idx - (b * NB - (b * (b + 1) >> 1)));
    }
    const bool diag = (bi == bj);

    const int row0 = bi * BM;
    const int col0 = bj * BM;

    const int lane   = threadIdx.x & 31;
    const int wid    = threadIdx.x >> 5;
    const int warp_m = wid & 3;
    const int warp_n = wid >> 2;
    const int laneM  = lane & 15;
    const int laneC  = lane >> 4;
    const int rq     = lane >> 2;
    const int cq     = lane & 3;

    int gRow[4];
    #pragma unroll
    for (int mi = 0; mi < 2; mi++)
        #pragma unroll
        for (int s = 0; s < 2; s++)
            gRow[mi * 2 + s] = row0 + warp_m * 32 + mi * 16 + s * 8 + rq;

    const char* gfb  = reinterpret_cast<const char*>(g_fb);
    const char* aSrc = gfb + (size_t)row0 * 512;
    const char* bSrc = gfb + (size_t)col0 * 512;

    // Prologue: fill both buffer pairs (chunks 0 and 1).
    load_chunk(sbase + 0 * CHUNK, aSrc);
    if (!diag) load_chunk(sbase + 2 * CHUNK, bSrc);
    CP_COMMIT();
    load_chunk(sbase + 1 * CHUNK, aSrc + 128);
    if (!diag) load_chunk(sbase + 3 * CHUNK, bSrc + 128);
    CP_COMMIT();

    float c[2][8][4];
    #pragma unroll
    for (int mi = 0; mi < 2; mi++)
        #pragma unroll
        for (int nj = 0; nj < 8; nj++)
            #pragma unroll
            for (int e = 0; e < 4; e++) c[mi][nj][e] = 0.f;

    #pragma unroll
    for (int kc = 0; kc < 4; kc++) {
        const int p = kc & 1;

        if (kc > 0) {
            __syncthreads();           // all warps done reading buffers p^1
            if (kc < 3) {
                load_chunk(sbase + (p ^ 1) * CHUNK, aSrc + (kc + 1) * 128);
                if (!diag)
                    load_chunk(sbase + (2 + (p ^ 1)) * CHUNK, bSrc + (kc + 1) * 128);
                CP_COMMIT();
            }
        }
        if (kc < 3) CP_WAIT1(); else CP_WAIT0();
        __syncthreads();

        const uint32_t bufA = sbase + p * CHUNK;
        const uint32_t bufB = diag ? bufA : (sbase + (2 + p) * CHUNK);

        #pragma unroll
        for (int ks = 0; ks < 4; ks++) {
            const int ch = ks * 2 + laneC;
            uint32_t a0[4], a1[4];
            {
                int r = warp_m * 32 + laneM;
                ldsm_x4(a0, bufA + r * 128 + ((ch ^ (r & 7)) << 4));
                int r2 = r + 16;
                ldsm_x4(a1, bufA + r2 * 128 + ((ch ^ (r2 & 7)) << 4));
            }
            #pragma unroll
            for (int ng = 0; ng < 4; ng++) {
                uint32_t bf[4];
                int nr = warp_n * 64 + ng * 16 + laneM;
                ldsm_x4(bf, bufB + nr * 128 + ((ch ^ (nr & 7)) << 4));
                mma_bf16(c[0][ng * 2],     a0, bf[0], bf[2]);
                mma_bf16(c[0][ng * 2 + 1], a0, bf[1], bf[3]);
                mma_bf16(c[1][ng * 2],     a1, bf[0], bf[2]);
                mma_bf16(c[1][ng * 2 + 1], a1, bf[1], bf[3]);
            }
        }
    }

    // ---- Epilogue: S only; accumulators are log2-domain -> raw ex2. ----
    float accS[4] = {0.f, 0.f, 0.f, 0.f};

    if (diag) {
        #pragma unroll
        for (int nj = 0; nj < 8; nj++) {
            const int gj0 = col0 + warp_n * 64 + nj * 8 + cq * 2;
            #pragma unroll
            for (int mi = 0; mi < 2; mi++) {
                #pragma unroll
                for (int s = 0; s < 2; s++) {
                    const int i4 = mi * 2 + s;
                    const int gi = gRow[i4];
                    float e0 = ex2f(c[mi][nj][s * 2 + 0]);
                    float e1 = ex2f(c[mi][nj][s * 2 + 1]);
                    if (gi != gj0)     accS[i4] += e0;
                    if (gi != gj0 + 1) accS[i4] += e1;
                }
            }
        }
    } else {
        float colS[16];
        #pragma unroll
        for (int i = 0; i < 16; i++) colS[i] = 0.f;

        #pragma unroll
        for (int nj = 0; nj < 8; nj++) {
            #pragma unroll
            for (int mi = 0; mi < 2; mi++) {
                #pragma unroll
                for (int s = 0; s < 2; s++) {
                    const int i4 = mi * 2 + s;
                    float e0 = ex2f(c[mi][nj][s * 2 + 0]);
                    float e1 = ex2f(c[mi][nj][s * 2 + 1]);
                    accS[i4] += e0 + e1;
                    colS[nj * 2]     += e0;
                    colS[nj * 2 + 1] += e1;
                }
            }
        }

        #pragma unroll
        for (int i = 0; i < 16; i++) {
            colS[i] += __shfl_xor_sync(0xFFFFFFFFu, colS[i], 4);
            colS[i] += __shfl_xor_sync(0xFFFFFFFFu, colS[i], 8);
            colS[i] += __shfl_xor_sync(0xFFFFFFFFu, colS[i], 16);
        }
        if (lane < 4) {
            #pragma unroll
            for (int nj = 0; nj < 8; nj++) {
                red_add_v2(&g_S[col0 + warp_n * 64 + nj * 8 + lane * 2],
                           colS[nj * 2], colS[nj * 2 + 1]);
            }
        }
    }

    #pragma unroll
    for (int i = 0; i < 4; i++) {
        accS[i] += __shfl_xor_sync(0xFFFFFFFFu, accS[i], 1);
        accS[i] += __shfl_xor_sync(0xFFFFFFFFu, accS[i], 2);
    }
    if (cq == 0) {
        #pragma unroll
        for (int i = 0; i < 4; i++)
            atomicAdd(&g_S[gRow[i]], accS[i]);
    }
}

// ---------------------------------------------------------------------------
// Kernel 3: per-row term via class sums. 4 rows per warp, loads batched.
// Last block writes the scalar and restores zero-invariants.
// ---------------------------------------------------------------------------
__global__ void finalize_kernel(float* __restrict__ out) {
    const int warp  = threadIdx.x >> 5;
    const int lane  = threadIdx.x & 31;
    const int rbase = blockIdx.x * 32 + warp * 4;

    int   lab[4];
    uint4 bv[4];
    float4 s0[4], s1[4];
    #pragma unroll
    for (int r = 0; r < 4; r++) lab[r] = g_lab[rbase + r];
    #pragma unroll
    for (int r = 0; r < 4; r++) {
        bv[r] = *reinterpret_cast<const uint4*>(
            &g_fb[(size_t)(rbase + r) * DDIM + lane * 8]);
        s0[r] = *reinterpret_cast<const float4*>(&g_sv[lab[r] * DDIM + lane * 8]);
        s1[r] = *reinterpret_cast<const float4*>(&g_sv[lab[r] * DDIM + lane * 8 + 4]);
    }

    float tsum = 0.0f;
    #pragma unroll
    for (int r = 0; r < 4; r++) {
        const __nv_bfloat162* bp = reinterpret_cast<const __nv_bfloat162*>(&bv[r]);
        float2 f0 = __bfloat1622float2(bp[0]);
        float2 f1 = __bfloat1622float2(bp[1]);
        float2 f2 = __bfloat1622float2(bp[2]);
        float2 f3 = __bfloat1622float2(bp[3]);

        float d = f0.x * s0[r].x + f0.y * s0[r].y + f1.x * s0[r].z + f1.y * s0[r].w
                + f2.x * s1[r].x + f2.y * s1[r].y + f3.x * s1[r].z + f3.y * s1[r].w;
        #pragma unroll
        for (int o = 16; o > 0; o >>= 1) d += __shfl_xor_sync(0xFFFFFFFFu, d, o);

        if (lane == 0) {
            float P  = (d - LOG2E_INVT) * LN2F;
            float Cf = (float)(g_cnt[lab[r]] - 1);
            float lz = __logf(g_S[rbase + r] + 1e-6f);
            tsum += (P - Cf * lz) / fmaxf(Cf, 1.0f);
            g_S[rbase + r] = 0.0f;      // zero-on-exit for next replay
        }
    }

    __shared__ float ws[8];
    __shared__ int   isLast;
    if (lane == 0) ws[warp] = tsum;
    __syncthreads();
    if (threadIdx.x == 0) {
        float s = 0.f;
        #pragma unroll
        for (int w = 0; w < 8; w++) s += ws[w];
        atomicAdd(&g_sum, s);
        __threadfence();
        int d_ = atomicAdd(&g_done, 1);
        isLast = (d_ == gridDim.x - 1);
    }
    __syncthreads();
    if (isLast) {
        if (threadIdx.x == 0) {
            __threadfence();
            out[0] = -g_sum / (float)NROW;
            g_sum  = 0.0f;
            g_done = 0;
        }
        for (int i = threadIdx.x; i < NCLS; i += 256) g_cnt[i] = 0;
    }
}

// ---------------------------------------------------------------------------
extern "C" void kernel_launch(void* const* d_in, const int* in_sizes, int n_in,
                              void* d_out, int out_size) {
    const float* feats = (const float*)d_in[0];
    const void*  labs  = d_in[1];
    float*       out   = (float*)d_out;

    cudaFuncSetAttribute(supcon_s_kernel,
                         cudaFuncAttributeMaxDynamicSharedMemorySize, SM_TOTAL);

    init_kernel<<<NROW / 256, 256>>>((const unsigned*)labs);

    // PDL only here: prep overlaps init's tail.
    cudaLaunchAttribute at[1];
    at[0].id = cudaLaunchAttributeProgrammaticStreamSerialization;
    at[0].val.programmaticStreamSerializationAllowed = 1;
    cudaLaunchConfig_t cfg = {};
    cfg.blockDim = {NTHREADS, 1, 1};
    cfg.gridDim  = {NROW / 8, 1, 1};
    cfg.attrs    = at;
    cfg.numAttrs = 1;
    cudaLaunchKernelEx(&cfg, prep_kernel, feats);

    supcon_s_kernel<<<NPAIRS, NTHREADS, SM_TOTAL>>>();

    finalize_kernel<<<FIN_BLOCKS, 256>>>(out);
}